// round 13
// baseline (speedup 1.0000x reference)
#include <cuda_runtime.h>
#include <cstdint>

#define MAXN 50000
#define MAXE 800000
#define MAXEA (MAXE + MAXN)
#define HC 256
#define HEADS 4
#define HID 64
#define INCH 16

// ---------------- scratch (static device globals; no allocation) ----------------
__device__ __align__(16) float g_bufA[MAXN * HC];
__device__ __align__(16) float g_bufB[MAXN * HC];
__device__ __align__(16) float g_agg[MAXN * HEADS * INCH];   // layer-1 aggregated x per head
__device__ __align__(16) float g_dsum[MAXN * HEADS];
__device__ __align__(16) float g_asrc[MAXN * HEADS];
__device__ __align__(16) float g_adst[MAXN * HEADS];
__device__ __align__(16) float g_proj[INCH * HEADS * 2];     // W1^T a_s / a_d projections
__device__ int g_csr_src[MAXEA];
__device__ int g_counts[MAXN];
__device__ int g_cursor[MAXN];
__device__ int g_offs[MAXN + 1];
__device__ int g_bsums[64];
__device__ int g_boffs[65];
__device__ int g_is64;

// ---------------- helpers ----------------
__device__ __forceinline__ float elu(float x) { return x > 0.f ? x : (__expf(x) - 1.f); }

__device__ __forceinline__ void load_edge(const void* ei, int E, int e, int& src, int& dst) {
    if (g_is64) {
        const long long* p = (const long long*)ei;
        src = (int)p[e];
        dst = (int)p[E + e];
    } else {
        const int* p = (const int*)ei;
        src = p[e];
        dst = p[E + e];
    }
}

// ---------------- init: zero counts/cursors + dtype detect (block 0) ----------------
__global__ void init_kernel(int* a, int* b, int n, const int* ei_words) {
    int i = blockIdx.x * blockDim.x + threadIdx.x;
    if (i < n) { a[i] = 0; b[i] = 0; }
    if (blockIdx.x == 0) {
        __shared__ int any_nonzero;
        if (threadIdx.x == 0) any_nonzero = 0;
        __syncthreads();
        for (int k = threadIdx.x; k < 512; k += blockDim.x)
            if (ei_words[2 * k + 1] != 0) any_nonzero = 1;
        __syncthreads();
        if (threadIdx.x == 0) g_is64 = any_nonzero ? 0 : 1;
    }
}

// ---------------- CSR construction ----------------
__global__ void count_kernel(const void* __restrict__ ei, int E, int EA, int* __restrict__ counts) {
    int e = blockIdx.x * blockDim.x + threadIdx.x;
    if (e >= EA) return;
    int src, dst;
    if (e >= E) { dst = e - E; }
    else        { load_edge(ei, E, e, src, dst); }
    atomicAdd(&counts[dst], 1);
}

__global__ void blocksum_kernel(const int* __restrict__ counts, int* __restrict__ bsums, int N) {
    __shared__ int sh[256];
    int base = blockIdx.x * 1024;
    int s = 0;
    for (int i = threadIdx.x; i < 1024; i += 256) {
        int idx = base + i;
        if (idx < N) s += counts[idx];
    }
    sh[threadIdx.x] = s;
    __syncthreads();
    for (int o = 128; o; o >>= 1) {
        if (threadIdx.x < o) sh[threadIdx.x] += sh[threadIdx.x + o];
        __syncthreads();
    }
    if (threadIdx.x == 0) bsums[blockIdx.x] = sh[0];
}

__global__ void bscan_kernel(const int* __restrict__ bsums, int* __restrict__ boffs, int nb) {
    __shared__ int sh[256];
    int v = (threadIdx.x < nb) ? bsums[threadIdx.x] : 0;
    sh[threadIdx.x] = v;
    __syncthreads();
    for (int o = 1; o < 256; o <<= 1) {
        int t = (threadIdx.x >= o) ? sh[threadIdx.x - o] : 0;
        __syncthreads();
        sh[threadIdx.x] += t;
        __syncthreads();
    }
    if (threadIdx.x < nb) boffs[threadIdx.x + 1] = sh[threadIdx.x];
    if (threadIdx.x == 0) boffs[0] = 0;
}

__global__ void scan3_kernel(const int* __restrict__ counts, const int* __restrict__ boffs,
                             int* __restrict__ offs, int N, int nb) {
    __shared__ int sh[256];
    int base = blockIdx.x * 1024 + threadIdx.x * 4;
    int c[4];
    int s = 0;
#pragma unroll
    for (int t = 0; t < 4; t++) {
        int idx = base + t;
        c[t] = (idx < N) ? counts[idx] : 0;
        s += c[t];
    }
    sh[threadIdx.x] = s;
    __syncthreads();
    for (int o = 1; o < 256; o <<= 1) {
        int t = (threadIdx.x >= o) ? sh[threadIdx.x - o] : 0;
        __syncthreads();
        sh[threadIdx.x] += t;
        __syncthreads();
    }
    int run = boffs[blockIdx.x] + (threadIdx.x ? sh[threadIdx.x - 1] : 0);
#pragma unroll
    for (int t = 0; t < 4; t++) {
        int idx = base + t;
        if (idx < N) offs[idx] = run;
        run += c[t];
    }
    if (blockIdx.x == 0 && threadIdx.x == 0) offs[N] = boffs[nb];
}

__global__ void fill_kernel(const void* __restrict__ ei, int E, int EA,
                            const int* __restrict__ offs, int* __restrict__ cursor,
                            int* __restrict__ csr_src) {
    int e = blockIdx.x * blockDim.x + threadIdx.x;
    if (e >= EA) return;
    int src, dst;
    if (e >= E) { src = e - E; dst = src; }
    else        { load_edge(ei, E, e, src, dst); }
    int p = offs[dst] + atomicAdd(&cursor[dst], 1);
    csr_src[p] = src;
}

// ---------------- layer 1 prep: proj[k][h][{s,d}] = sum_c W1[k, h*64+c] * a_{s,d}[h,c] ----------
__global__ void prep1_kernel(const float* __restrict__ W1, const float* __restrict__ as1,
                             const float* __restrict__ ad1, float* __restrict__ proj) {
    int t = threadIdx.x;                 // 0..63 : (k,h)
    if (t >= INCH * HEADS) return;
    int k = t >> 2, h = t & 3;
    float ss = 0.f, sd = 0.f;
#pragma unroll
    for (int c = 0; c < HID; c++) {
        float w = W1[k * HC + h * HID + c];
        ss = fmaf(w, as1[h * HID + c], ss);
        sd = fmaf(w, ad1[h * HID + c], sd);
    }
    proj[(k * HEADS + h) * 2 + 0] = ss;
    proj[(k * HEADS + h) * 2 + 1] = sd;
}

// ---------------- layer 1 attention scalars straight from x ----------------
// thread per (n,h)
__global__ void alpha1_kernel(const float* __restrict__ x, const float* __restrict__ proj,
                              float* __restrict__ asrc, float* __restrict__ adst, int N) {
    __shared__ float pr[INCH * HEADS * 2];
    for (int i = threadIdx.x; i < INCH * HEADS * 2; i += blockDim.x) pr[i] = proj[i];
    __syncthreads();
    int t = blockIdx.x * blockDim.x + threadIdx.x;
    if (t >= N * HEADS) return;
    int n = t >> 2, h = t & 3;
    const float* xr = x + (size_t)n * INCH;
    float ss = 0.f, sd = 0.f;
#pragma unroll
    for (int k = 0; k < INCH; k++) {
        float v = xr[k];
        ss = fmaf(v, pr[(k * HEADS + h) * 2 + 0], ss);
        sd = fmaf(v, pr[(k * HEADS + h) * 2 + 1], sd);
    }
    asrc[t] = ss;
    adst[t] = sd;
}

// ---------------- layer 1 gather in INPUT space: agg[n,h,:] = sum_e w_e x[src_e] ----------------
// one warp per node; lane: h = lane>>3, float2 of x dims (lane&7)*2
__global__ void gather1_kernel(const int* __restrict__ offs, const int* __restrict__ csr_src,
                               const float* __restrict__ asrc, const float* __restrict__ adst,
                               const float* __restrict__ x, float* __restrict__ agg,
                               float* __restrict__ dsum, int N) {
    int n = (blockIdx.x * blockDim.x + threadIdx.x) >> 5;
    if (n >= N) return;
    int lane = threadIdx.x & 31;
    int h = lane >> 3;
    int k2 = (lane & 7) * 2;
    float adh = __ldg(&adst[n * 4 + h]);
    int beg = offs[n], end = offs[n + 1];

    float a0 = 0.f, a1 = 0.f, ds = 0.f;
#pragma unroll 2
    for (int i = beg; i < end; i++) {
        int src = __ldg(&csr_src[i]);
        float e = __ldg(&asrc[src * 4 + h]) + adh;
        float wv = __expf(e > 0.f ? e : 0.2f * e);
        ds += wv;
        float2 xv = *(const float2*)(x + (size_t)src * INCH + k2);
        a0 = fmaf(wv, xv.x, a0);
        a1 = fmaf(wv, xv.y, a1);
    }
    float2* op = (float2*)(agg + (size_t)n * 64 + h * INCH + k2);
    *op = make_float2(a0, a1);
    if ((lane & 7) == 0) dsum[n * 4 + h] = ds;
}

// ---------------- layer 1 post: out[n,j] = elu( (agg[n,h,:]·W1[:,j]) / dsum + b1[j] ) ------------
// 256 threads = columns, 16 nodes per block
__global__ void post1_kernel(const float* __restrict__ agg, const float* __restrict__ dsum,
                             const float* __restrict__ W1, const float* __restrict__ b1,
                             float* __restrict__ out, int N) {
    __shared__ float ag[16 * 64];
    __shared__ float dsm[16 * 4];
    int n0 = blockIdx.x * 16;
    int j = threadIdx.x;
    int h = j >> 6;
    for (int i = threadIdx.x; i < 16 * 64; i += 256) {
        int node = n0 + i / 64;
        ag[i] = (node < N) ? agg[(size_t)n0 * 64 + i] : 0.f;
    }
    if (threadIdx.x < 64) {
        int node = n0 + threadIdx.x / 4;
        dsm[threadIdx.x] = (node < N) ? dsum[n0 * 4 + threadIdx.x] : 1.f;
    }
    __syncthreads();

    float wreg[INCH];
#pragma unroll
    for (int k = 0; k < INCH; k++) wreg[k] = W1[k * HC + j];
    float bj = b1[j];

    for (int i = 0; i < 16; i++) {
        int node = n0 + i;
        if (node >= N) break;
        const float* ar = ag + i * 64 + h * INCH;
        float s = 0.f;
#pragma unroll
        for (int k = 0; k < INCH; k++) s = fmaf(ar[k], wreg[k], s);
        float v = s / dsm[i * 4 + h] + bj;
        out[(size_t)node * HC + j] = elu(v);
    }
}

// ---------------- layer-2 node transform: H = X @ W2, packed f32x2 over node pairs ----------------
template <int K>
__global__ void transform_kernel(const float* __restrict__ X, const float* __restrict__ W,
                                 float* __restrict__ H, int N) {
    constexpr int NPB = 64;
    constexpr int PAIRS = NPB / 2;
    constexpr int RSTR = PAIRS + 1;
    constexpr int KC = (K <= 128) ? K : 128;
    __shared__ unsigned long long xs2[KC * RSTR];

    int n0 = blockIdx.x * NPB;
    int j = threadIdx.x;

    unsigned long long acc[PAIRS];
#pragma unroll
    for (int p = 0; p < PAIRS; p++) acc[p] = 0ull;

    for (int kc0 = 0; kc0 < K; kc0 += KC) {
        __syncthreads();
        for (int idx = threadIdx.x; idx < NPB * KC; idx += 256) {
            int i = idx / KC, kk = idx % KC;
            int node = n0 + i;
            float v = (node < N) ? X[(size_t)node * K + kc0 + kk] : 0.f;
            ((float*)xs2)[(kk * RSTR + (i >> 1)) * 2 + (i & 1)] = v;
        }
        __syncthreads();

        for (int kk = 0; kk < KC; kk++) {
            float wv = W[(kc0 + kk) * HC + j];
            unsigned long long wv2;
            asm("mov.b64 %0, {%1, %1};" : "=l"(wv2) : "f"(wv));
            const unsigned long long* row = xs2 + kk * RSTR;
#pragma unroll
            for (int p = 0; p < PAIRS; p++) {
                asm("fma.rn.f32x2 %0, %1, %2, %0;" : "+l"(acc[p]) : "l"(row[p]), "l"(wv2));
            }
        }
    }

#pragma unroll
    for (int p = 0; p < PAIRS; p++) {
        float lo, hi;
        asm("mov.b64 {%0, %1}, %2;" : "=f"(lo), "=f"(hi) : "l"(acc[p]));
        int na = n0 + 2 * p, nb = na + 1;
        if (na < N) H[(size_t)na * HC + j] = lo;
        if (nb < N) H[(size_t)nb * HC + j] = hi;
    }
}

// ---------------- per-node attention scalars (layer 2) ----------------
__global__ void alpha_kernel(const float* __restrict__ H, const float* __restrict__ a_s,
                             const float* __restrict__ a_d, float* __restrict__ asrc,
                             float* __restrict__ adst, int N) {
    int wid = (blockIdx.x * blockDim.x + threadIdx.x) >> 5;
    int lane = threadIdx.x & 31;
    if (wid >= N * HEADS) return;
    int n = wid >> 2, h = wid & 3;
    const float* row = H + (size_t)n * HC + h * HID;
    float v0 = row[lane], v1 = row[lane + 32];
    float s1 = v0 * a_s[h * HID + lane] + v1 * a_s[h * HID + lane + 32];
    float s2 = v0 * a_d[h * HID + lane] + v1 * a_d[h * HID + lane + 32];
#pragma unroll
    for (int o = 16; o; o >>= 1) {
        s1 += __shfl_down_sync(0xffffffffu, s1, o);
        s2 += __shfl_down_sync(0xffffffffu, s2, o);
    }
    if (lane == 0) { asrc[wid] = s1; adst[wid] = s2; }
}

// ---------------- layer-2 fused gather: attention + softmax + aggregate ----------------
__global__ void gather_kernel(const int* __restrict__ offs, const int* __restrict__ csr_src,
                              const float* __restrict__ asrc, const float* __restrict__ adst,
                              const float* __restrict__ H, float* __restrict__ out, int N) {
    int n = (blockIdx.x * blockDim.x + threadIdx.x) >> 5;
    if (n >= N) return;
    int lane = threadIdx.x & 31;
    int h = lane >> 3;
    int cbase = lane * 8;
    float adh = __ldg(&adst[n * 4 + h]);
    int beg = offs[n], end = offs[n + 1];

    float acc[8];
#pragma unroll
    for (int j = 0; j < 8; j++) acc[j] = 0.f;
    float dsm = 0.f;

#pragma unroll 2
    for (int i = beg; i < end; i++) {
        int src = __ldg(&csr_src[i]);
        float e = __ldg(&asrc[src * 4 + h]) + adh;
        float wv = __expf(e > 0.f ? e : 0.2f * e);
        dsm += wv;
        const float4* hp = (const float4*)(H + (size_t)src * HC + cbase);
        float4 v0 = hp[0];
        float4 v1 = hp[1];
        acc[0] = fmaf(wv, v0.x, acc[0]);
        acc[1] = fmaf(wv, v0.y, acc[1]);
        acc[2] = fmaf(wv, v0.z, acc[2]);
        acc[3] = fmaf(wv, v0.w, acc[3]);
        acc[4] = fmaf(wv, v1.x, acc[4]);
        acc[5] = fmaf(wv, v1.y, acc[5]);
        acc[6] = fmaf(wv, v1.z, acc[6]);
        acc[7] = fmaf(wv, v1.w, acc[7]);
    }

    float inv = 1.f / dsm;
    float4* op = (float4*)(out + (size_t)n * HC + cbase);
    op[0] = make_float4(acc[0] * inv, acc[1] * inv, acc[2] * inv, acc[3] * inv);
    op[1] = make_float4(acc[4] * inv, acc[5] * inv, acc[6] * inv, acc[7] * inv);
}

// ---------------- layer-2 epilogue: head-mean + bias + ELU, then @Wc + bc ----------------
__global__ void final_kernel(const float* __restrict__ acc, const float* __restrict__ b2,
                             const float* __restrict__ Wc, const float* __restrict__ bc,
                             float* __restrict__ out, int N) {
    __shared__ float feat[4][HID];
    int nl = threadIdx.x >> 6, c = threadIdx.x & 63;
    int n = blockIdx.x * 4 + nl;
    if (n < N) {
        float f = 0.f;
#pragma unroll
        for (int h = 0; h < HEADS; h++)
            f += acc[(size_t)n * HC + h * HID + c];
        f = 0.25f * f + b2[c];
        feat[nl][c] = elu(f);
    }
    __syncthreads();
    if (threadIdx.x < 32) {
        int nl2 = threadIdx.x >> 3, o = threadIdx.x & 7;
        int n2 = blockIdx.x * 4 + nl2;
        if (n2 < N) {
            float s = bc[o];
#pragma unroll 8
            for (int cc = 0; cc < HID; cc++)
                s = fmaf(feat[nl2][cc], Wc[cc * 8 + o], s);
            out[n2 * 8 + o] = s;
        }
    }
}

// ---------------- launch ----------------
extern "C" void kernel_launch(void* const* d_in, const int* in_sizes, int n_in,
                              void* d_out, int out_size) {
    const float* x   = (const float*)d_in[0];
    const void*  ei  = d_in[1];
    const float* W1  = (const float*)d_in[2];
    const float* as1 = (const float*)d_in[3];
    const float* ad1 = (const float*)d_in[4];
    const float* b1  = (const float*)d_in[5];
    const float* W2  = (const float*)d_in[6];
    const float* as2 = (const float*)d_in[7];
    const float* ad2 = (const float*)d_in[8];
    const float* b2  = (const float*)d_in[9];
    const float* Wc  = (const float*)d_in[10];
    const float* bc  = (const float*)d_in[11];
    float* out = (float*)d_out;

    int N  = in_sizes[0] / 16;
    int E  = in_sizes[1] / 2;
    int EA = E + N;
    int nb = (N + 1023) / 1024;

    float *bufA, *bufB, *agg, *dsum, *asrc, *adst, *proj;
    int *csr_src, *counts, *cursor, *offs, *bsums, *boffs;
    cudaGetSymbolAddress((void**)&bufA,    g_bufA);
    cudaGetSymbolAddress((void**)&bufB,    g_bufB);
    cudaGetSymbolAddress((void**)&agg,     g_agg);
    cudaGetSymbolAddress((void**)&dsum,    g_dsum);
    cudaGetSymbolAddress((void**)&asrc,    g_asrc);
    cudaGetSymbolAddress((void**)&adst,    g_adst);
    cudaGetSymbolAddress((void**)&proj,    g_proj);
    cudaGetSymbolAddress((void**)&csr_src, g_csr_src);
    cudaGetSymbolAddress((void**)&counts,  g_counts);
    cudaGetSymbolAddress((void**)&cursor,  g_cursor);
    cudaGetSymbolAddress((void**)&offs,    g_offs);
    cudaGetSymbolAddress((void**)&bsums,   g_bsums);
    cudaGetSymbolAddress((void**)&boffs,   g_boffs);

    const int B = 256;
    int gridT      = (N + 63) / 64;
    int gridAlpha1 = (N * HEADS + B - 1) / B;
    int gridAlpha  = (N * HEADS * 32 + B - 1) / B;
    int gridEdge   = (EA + B - 1) / B;
    int gridGather = (N * 32 + B - 1) / B;
    int gridPost1  = (N + 15) / 16;
    int gridFinal  = (N + 3) / 4;
    int gridZeroN  = (N + B - 1) / B;

    // ----- init + CSR structure -----
    init_kernel<<<gridZeroN, B>>>(counts, cursor, N, (const int*)ei);
    count_kernel<<<gridEdge, B>>>(ei, E, EA, counts);
    blocksum_kernel<<<nb, B>>>(counts, bsums, N);
    bscan_kernel<<<1, B>>>(bsums, boffs, nb);
    scan3_kernel<<<nb, B>>>(counts, boffs, offs, N, nb);
    fill_kernel<<<gridEdge, B>>>(ei, E, EA, offs, cursor, csr_src);

    // ----- layer 1 (input-space aggregation) -----
    prep1_kernel<<<1, 64>>>(W1, as1, ad1, proj);
    alpha1_kernel<<<gridAlpha1, B>>>(x, proj, asrc, adst, N);
    gather1_kernel<<<gridGather, B>>>(offs, csr_src, asrc, adst, x, agg, dsum, N);
    post1_kernel<<<gridPost1, B>>>(agg, dsum, W1, b1, bufB, N);

    // ----- layer 2 -----
    transform_kernel<256><<<gridT, B>>>(bufB, W2, bufA, N);
    alpha_kernel<<<gridAlpha, B>>>(bufA, as2, ad2, asrc, adst, N);
    gather_kernel<<<gridGather, B>>>(offs, csr_src, asrc, adst, bufA, bufB, N);

    // ----- head-mean + classifier -----
    final_kernel<<<gridFinal, B>>>(bufB, b2, Wc, bc, out, N);
}

// round 14
// speedup vs baseline: 1.0025x; 1.0025x over previous
#include <cuda_runtime.h>
#include <cstdint>

#define MAXN 50000
#define MAXE 800000
#define MAXEA (MAXE + MAXN)
#define HC 256
#define HEADS 4
#define HID 64
#define INCH 16

// ---------------- scratch (static device globals; no allocation) ----------------
__device__ __align__(16) float g_bufA[MAXN * HC];
__device__ __align__(16) float g_bufB[MAXN * HC];
__device__ __align__(16) float g_agg[MAXN * HEADS * INCH];   // layer-1 aggregated x per head
__device__ __align__(16) float g_dsum[MAXN * HEADS];
__device__ __align__(16) float g_asrc[MAXN * HEADS];
__device__ __align__(16) float g_adst[MAXN * HEADS];
__device__ __align__(16) float g_proj[INCH * HEADS * 2];     // W1^T a_s / a_d projections
__device__ int g_csr_src[MAXEA];
__device__ int g_counts[MAXN];
__device__ int g_cursor[MAXN];
__device__ int g_offs[MAXN + 1];
__device__ int g_bsums[64];
__device__ int g_boffs[65];
__device__ int g_is64;

// ---------------- helpers ----------------
__device__ __forceinline__ float elu(float x) { return x > 0.f ? x : (__expf(x) - 1.f); }

__device__ __forceinline__ void load_edge(const void* ei, int E, int e, int& src, int& dst) {
    if (g_is64) {
        const long long* p = (const long long*)ei;
        src = (int)p[e];
        dst = (int)p[E + e];
    } else {
        const int* p = (const int*)ei;
        src = p[e];
        dst = p[E + e];
    }
}

// ---------------- init: zero counts/cursors + dtype detect (block 0) ----------------
__global__ void init_kernel(int* a, int* b, int n, const int* ei_words) {
    int i = blockIdx.x * blockDim.x + threadIdx.x;
    if (i < n) { a[i] = 0; b[i] = 0; }
    if (blockIdx.x == 0) {
        __shared__ int any_nonzero;
        if (threadIdx.x == 0) any_nonzero = 0;
        __syncthreads();
        for (int k = threadIdx.x; k < 512; k += blockDim.x)
            if (ei_words[2 * k + 1] != 0) any_nonzero = 1;
        __syncthreads();
        if (threadIdx.x == 0) g_is64 = any_nonzero ? 0 : 1;
    }
}

// ---------------- CSR construction ----------------
__global__ void count_kernel(const void* __restrict__ ei, int E, int EA, int* __restrict__ counts) {
    int e = blockIdx.x * blockDim.x + threadIdx.x;
    if (e >= EA) return;
    int src, dst;
    if (e >= E) { dst = e - E; }
    else        { load_edge(ei, E, e, src, dst); }
    atomicAdd(&counts[dst], 1);
}

__global__ void blocksum_kernel(const int* __restrict__ counts, int* __restrict__ bsums, int N) {
    __shared__ int sh[256];
    int base = blockIdx.x * 1024;
    int s = 0;
    for (int i = threadIdx.x; i < 1024; i += 256) {
        int idx = base + i;
        if (idx < N) s += counts[idx];
    }
    sh[threadIdx.x] = s;
    __syncthreads();
    for (int o = 128; o; o >>= 1) {
        if (threadIdx.x < o) sh[threadIdx.x] += sh[threadIdx.x + o];
        __syncthreads();
    }
    if (threadIdx.x == 0) bsums[blockIdx.x] = sh[0];
}

__global__ void bscan_kernel(const int* __restrict__ bsums, int* __restrict__ boffs, int nb) {
    __shared__ int sh[256];
    int v = (threadIdx.x < nb) ? bsums[threadIdx.x] : 0;
    sh[threadIdx.x] = v;
    __syncthreads();
    for (int o = 1; o < 256; o <<= 1) {
        int t = (threadIdx.x >= o) ? sh[threadIdx.x - o] : 0;
        __syncthreads();
        sh[threadIdx.x] += t;
        __syncthreads();
    }
    if (threadIdx.x < nb) boffs[threadIdx.x + 1] = sh[threadIdx.x];
    if (threadIdx.x == 0) boffs[0] = 0;
}

__global__ void scan3_kernel(const int* __restrict__ counts, const int* __restrict__ boffs,
                             int* __restrict__ offs, int N, int nb) {
    __shared__ int sh[256];
    int base = blockIdx.x * 1024 + threadIdx.x * 4;
    int c[4];
    int s = 0;
#pragma unroll
    for (int t = 0; t < 4; t++) {
        int idx = base + t;
        c[t] = (idx < N) ? counts[idx] : 0;
        s += c[t];
    }
    sh[threadIdx.x] = s;
    __syncthreads();
    for (int o = 1; o < 256; o <<= 1) {
        int t = (threadIdx.x >= o) ? sh[threadIdx.x - o] : 0;
        __syncthreads();
        sh[threadIdx.x] += t;
        __syncthreads();
    }
    int run = boffs[blockIdx.x] + (threadIdx.x ? sh[threadIdx.x - 1] : 0);
#pragma unroll
    for (int t = 0; t < 4; t++) {
        int idx = base + t;
        if (idx < N) offs[idx] = run;
        run += c[t];
    }
    if (blockIdx.x == 0 && threadIdx.x == 0) offs[N] = boffs[nb];
}

__global__ void fill_kernel(const void* __restrict__ ei, int E, int EA,
                            const int* __restrict__ offs, int* __restrict__ cursor,
                            int* __restrict__ csr_src) {
    int e = blockIdx.x * blockDim.x + threadIdx.x;
    if (e >= EA) return;
    int src, dst;
    if (e >= E) { src = e - E; dst = src; }
    else        { load_edge(ei, E, e, src, dst); }
    int p = offs[dst] + atomicAdd(&cursor[dst], 1);
    csr_src[p] = src;
}

// ---------------- layer 1 prep: proj[k][h][{s,d}] = sum_c W1[k, h*64+c] * a_{s,d}[h,c] ----------
__global__ void prep1_kernel(const float* __restrict__ W1, const float* __restrict__ as1,
                             const float* __restrict__ ad1, float* __restrict__ proj) {
    int t = threadIdx.x;                 // 0..63 : (k,h)
    if (t >= INCH * HEADS) return;
    int k = t >> 2, h = t & 3;
    float ss = 0.f, sd = 0.f;
#pragma unroll
    for (int c = 0; c < HID; c++) {
        float w = W1[k * HC + h * HID + c];
        ss = fmaf(w, as1[h * HID + c], ss);
        sd = fmaf(w, ad1[h * HID + c], sd);
    }
    proj[(k * HEADS + h) * 2 + 0] = ss;
    proj[(k * HEADS + h) * 2 + 1] = sd;
}

// ---------------- layer 1 attention scalars straight from x ----------------
// thread per (n,h)
__global__ void alpha1_kernel(const float* __restrict__ x, const float* __restrict__ proj,
                              float* __restrict__ asrc, float* __restrict__ adst, int N) {
    __shared__ float pr[INCH * HEADS * 2];
    for (int i = threadIdx.x; i < INCH * HEADS * 2; i += blockDim.x) pr[i] = proj[i];
    __syncthreads();
    int t = blockIdx.x * blockDim.x + threadIdx.x;
    if (t >= N * HEADS) return;
    int n = t >> 2, h = t & 3;
    const float* xr = x + (size_t)n * INCH;
    float ss = 0.f, sd = 0.f;
#pragma unroll
    for (int k = 0; k < INCH; k++) {
        float v = xr[k];
        ss = fmaf(v, pr[(k * HEADS + h) * 2 + 0], ss);
        sd = fmaf(v, pr[(k * HEADS + h) * 2 + 1], sd);
    }
    asrc[t] = ss;
    adst[t] = sd;
}

// ---------------- layer 1 gather in INPUT space: agg[n,h,:] = sum_e w_e x[src_e] ----------------
// one warp per node; lane: h = lane>>3, float2 of x dims (lane&7)*2
__global__ void gather1_kernel(const int* __restrict__ offs, const int* __restrict__ csr_src,
                               const float* __restrict__ asrc, const float* __restrict__ adst,
                               const float* __restrict__ x, float* __restrict__ agg,
                               float* __restrict__ dsum, int N) {
    int n = (blockIdx.x * blockDim.x + threadIdx.x) >> 5;
    if (n >= N) return;
    int lane = threadIdx.x & 31;
    int h = lane >> 3;
    int k2 = (lane & 7) * 2;
    float adh = __ldg(&adst[n * 4 + h]);
    int beg = offs[n], end = offs[n + 1];

    float a0 = 0.f, a1 = 0.f, ds = 0.f;
#pragma unroll 2
    for (int i = beg; i < end; i++) {
        int src = __ldg(&csr_src[i]);
        float e = __ldg(&asrc[src * 4 + h]) + adh;
        float wv = __expf(e > 0.f ? e : 0.2f * e);
        ds += wv;
        float2 xv = *(const float2*)(x + (size_t)src * INCH + k2);
        a0 = fmaf(wv, xv.x, a0);
        a1 = fmaf(wv, xv.y, a1);
    }
    float2* op = (float2*)(agg + (size_t)n * 64 + h * INCH + k2);
    *op = make_float2(a0, a1);
    if ((lane & 7) == 0) dsum[n * 4 + h] = ds;
}

// ---------------- layer 1 post: out[n,j] = elu( (agg[n,h,:]·W1[:,j]) / dsum + b1[j] ) ------------
// 256 threads = columns, 16 nodes per block
__global__ void post1_kernel(const float* __restrict__ agg, const float* __restrict__ dsum,
                             const float* __restrict__ W1, const float* __restrict__ b1,
                             float* __restrict__ out, int N) {
    __shared__ float ag[16 * 64];
    __shared__ float dsm[16 * 4];
    int n0 = blockIdx.x * 16;
    int j = threadIdx.x;
    int h = j >> 6;
    for (int i = threadIdx.x; i < 16 * 64; i += 256) {
        int node = n0 + i / 64;
        ag[i] = (node < N) ? agg[(size_t)n0 * 64 + i] : 0.f;
    }
    if (threadIdx.x < 64) {
        int node = n0 + threadIdx.x / 4;
        dsm[threadIdx.x] = (node < N) ? dsum[n0 * 4 + threadIdx.x] : 1.f;
    }
    __syncthreads();

    float wreg[INCH];
#pragma unroll
    for (int k = 0; k < INCH; k++) wreg[k] = W1[k * HC + j];
    float bj = b1[j];

    for (int i = 0; i < 16; i++) {
        int node = n0 + i;
        if (node >= N) break;
        const float* ar = ag + i * 64 + h * INCH;
        float s = 0.f;
#pragma unroll
        for (int k = 0; k < INCH; k++) s = fmaf(ar[k], wreg[k], s);
        float v = s / dsm[i * 4 + h] + bj;
        out[(size_t)node * HC + j] = elu(v);
    }
}

// ---------------- layer-2 node transform: H = X @ W2, packed f32x2 over node pairs ----------------
template <int K>
__global__ void transform_kernel(const float* __restrict__ X, const float* __restrict__ W,
                                 float* __restrict__ H, int N) {
    constexpr int NPB = 64;
    constexpr int PAIRS = NPB / 2;
    constexpr int RSTR = PAIRS + 1;
    constexpr int KC = (K <= 128) ? K : 128;
    __shared__ unsigned long long xs2[KC * RSTR];

    int n0 = blockIdx.x * NPB;
    int j = threadIdx.x;

    unsigned long long acc[PAIRS];
#pragma unroll
    for (int p = 0; p < PAIRS; p++) acc[p] = 0ull;

    for (int kc0 = 0; kc0 < K; kc0 += KC) {
        __syncthreads();
        for (int idx = threadIdx.x; idx < NPB * KC; idx += 256) {
            int i = idx / KC, kk = idx % KC;
            int node = n0 + i;
            float v = (node < N) ? X[(size_t)node * K + kc0 + kk] : 0.f;
            ((float*)xs2)[(kk * RSTR + (i >> 1)) * 2 + (i & 1)] = v;
        }
        __syncthreads();

        for (int kk = 0; kk < KC; kk++) {
            float wv = W[(kc0 + kk) * HC + j];
            unsigned long long wv2;
            asm("mov.b64 %0, {%1, %1};" : "=l"(wv2) : "f"(wv));
            const unsigned long long* row = xs2 + kk * RSTR;
#pragma unroll
            for (int p = 0; p < PAIRS; p++) {
                asm("fma.rn.f32x2 %0, %1, %2, %0;" : "+l"(acc[p]) : "l"(row[p]), "l"(wv2));
            }
        }
    }

#pragma unroll
    for (int p = 0; p < PAIRS; p++) {
        float lo, hi;
        asm("mov.b64 {%0, %1}, %2;" : "=f"(lo), "=f"(hi) : "l"(acc[p]));
        int na = n0 + 2 * p, nb = na + 1;
        if (na < N) H[(size_t)na * HC + j] = lo;
        if (nb < N) H[(size_t)nb * HC + j] = hi;
    }
}

// ---------------- per-node attention scalars (layer 2) ----------------
__global__ void alpha_kernel(const float* __restrict__ H, const float* __restrict__ a_s,
                             const float* __restrict__ a_d, float* __restrict__ asrc,
                             float* __restrict__ adst, int N) {
    int wid = (blockIdx.x * blockDim.x + threadIdx.x) >> 5;
    int lane = threadIdx.x & 31;
    if (wid >= N * HEADS) return;
    int n = wid >> 2, h = wid & 3;
    const float* row = H + (size_t)n * HC + h * HID;
    float v0 = row[lane], v1 = row[lane + 32];
    float s1 = v0 * a_s[h * HID + lane] + v1 * a_s[h * HID + lane + 32];
    float s2 = v0 * a_d[h * HID + lane] + v1 * a_d[h * HID + lane + 32];
#pragma unroll
    for (int o = 16; o; o >>= 1) {
        s1 += __shfl_down_sync(0xffffffffu, s1, o);
        s2 += __shfl_down_sync(0xffffffffu, s2, o);
    }
    if (lane == 0) { asrc[wid] = s1; adst[wid] = s2; }
}

// ---------------- layer-2 fused gather: attention + softmax + aggregate ----------------
__global__ void gather_kernel(const int* __restrict__ offs, const int* __restrict__ csr_src,
                              const float* __restrict__ asrc, const float* __restrict__ adst,
                              const float* __restrict__ H, float* __restrict__ out, int N) {
    int n = (blockIdx.x * blockDim.x + threadIdx.x) >> 5;
    if (n >= N) return;
    int lane = threadIdx.x & 31;
    int h = lane >> 3;
    int cbase = lane * 8;
    float adh = __ldg(&adst[n * 4 + h]);
    int beg = offs[n], end = offs[n + 1];

    float acc[8];
#pragma unroll
    for (int j = 0; j < 8; j++) acc[j] = 0.f;
    float dsm = 0.f;

#pragma unroll 2
    for (int i = beg; i < end; i++) {
        int src = __ldg(&csr_src[i]);
        float e = __ldg(&asrc[src * 4 + h]) + adh;
        float wv = __expf(e > 0.f ? e : 0.2f * e);
        dsm += wv;
        const float4* hp = (const float4*)(H + (size_t)src * HC + cbase);
        float4 v0 = hp[0];
        float4 v1 = hp[1];
        acc[0] = fmaf(wv, v0.x, acc[0]);
        acc[1] = fmaf(wv, v0.y, acc[1]);
        acc[2] = fmaf(wv, v0.z, acc[2]);
        acc[3] = fmaf(wv, v0.w, acc[3]);
        acc[4] = fmaf(wv, v1.x, acc[4]);
        acc[5] = fmaf(wv, v1.y, acc[5]);
        acc[6] = fmaf(wv, v1.z, acc[6]);
        acc[7] = fmaf(wv, v1.w, acc[7]);
    }

    float inv = 1.f / dsm;
    float4* op = (float4*)(out + (size_t)n * HC + cbase);
    op[0] = make_float4(acc[0] * inv, acc[1] * inv, acc[2] * inv, acc[3] * inv);
    op[1] = make_float4(acc[4] * inv, acc[5] * inv, acc[6] * inv, acc[7] * inv);
}

// ---------------- layer-2 epilogue: head-mean + bias + ELU, then @Wc + bc ----------------
__global__ void final_kernel(const float* __restrict__ acc, const float* __restrict__ b2,
                             const float* __restrict__ Wc, const float* __restrict__ bc,
                             float* __restrict__ out, int N) {
    __shared__ float feat[4][HID];
    int nl = threadIdx.x >> 6, c = threadIdx.x & 63;
    int n = blockIdx.x * 4 + nl;
    if (n < N) {
        float f = 0.f;
#pragma unroll
        for (int h = 0; h < HEADS; h++)
            f += acc[(size_t)n * HC + h * HID + c];
        f = 0.25f * f + b2[c];
        feat[nl][c] = elu(f);
    }
    __syncthreads();
    if (threadIdx.x < 32) {
        int nl2 = threadIdx.x >> 3, o = threadIdx.x & 7;
        int n2 = blockIdx.x * 4 + nl2;
        if (n2 < N) {
            float s = bc[o];
#pragma unroll 8
            for (int cc = 0; cc < HID; cc++)
                s = fmaf(feat[nl2][cc], Wc[cc * 8 + o], s);
            out[n2 * 8 + o] = s;
        }
    }
}

// ---------------- launch ----------------
extern "C" void kernel_launch(void* const* d_in, const int* in_sizes, int n_in,
                              void* d_out, int out_size) {
    const float* x   = (const float*)d_in[0];
    const void*  ei  = d_in[1];
    const float* W1  = (const float*)d_in[2];
    const float* as1 = (const float*)d_in[3];
    const float* ad1 = (const float*)d_in[4];
    const float* b1  = (const float*)d_in[5];
    const float* W2  = (const float*)d_in[6];
    const float* as2 = (const float*)d_in[7];
    const float* ad2 = (const float*)d_in[8];
    const float* b2  = (const float*)d_in[9];
    const float* Wc  = (const float*)d_in[10];
    const float* bc  = (const float*)d_in[11];
    float* out = (float*)d_out;

    int N  = in_sizes[0] / 16;
    int E  = in_sizes[1] / 2;
    int EA = E + N;
    int nb = (N + 1023) / 1024;

    float *bufA, *bufB, *agg, *dsum, *asrc, *adst, *proj;
    int *csr_src, *counts, *cursor, *offs, *bsums, *boffs;
    cudaGetSymbolAddress((void**)&bufA,    g_bufA);
    cudaGetSymbolAddress((void**)&bufB,    g_bufB);
    cudaGetSymbolAddress((void**)&agg,     g_agg);
    cudaGetSymbolAddress((void**)&dsum,    g_dsum);
    cudaGetSymbolAddress((void**)&asrc,    g_asrc);
    cudaGetSymbolAddress((void**)&adst,    g_adst);
    cudaGetSymbolAddress((void**)&proj,    g_proj);
    cudaGetSymbolAddress((void**)&csr_src, g_csr_src);
    cudaGetSymbolAddress((void**)&counts,  g_counts);
    cudaGetSymbolAddress((void**)&cursor,  g_cursor);
    cudaGetSymbolAddress((void**)&offs,    g_offs);
    cudaGetSymbolAddress((void**)&bsums,   g_bsums);
    cudaGetSymbolAddress((void**)&boffs,   g_boffs);

    const int B = 256;
    int gridT      = (N + 63) / 64;
    int gridAlpha1 = (N * HEADS + B - 1) / B;
    int gridAlpha  = (N * HEADS * 32 + B - 1) / B;
    int gridEdge   = (EA + B - 1) / B;
    int gridGather = (N * 32 + B - 1) / B;
    int gridPost1  = (N + 15) / 16;
    int gridFinal  = (N + 3) / 4;
    int gridZeroN  = (N + B - 1) / B;

    // ----- init + CSR structure -----
    init_kernel<<<gridZeroN, B>>>(counts, cursor, N, (const int*)ei);
    count_kernel<<<gridEdge, B>>>(ei, E, EA, counts);
    blocksum_kernel<<<nb, B>>>(counts, bsums, N);
    bscan_kernel<<<1, B>>>(bsums, boffs, nb);
    scan3_kernel<<<nb, B>>>(counts, boffs, offs, N, nb);
    fill_kernel<<<gridEdge, B>>>(ei, E, EA, offs, cursor, csr_src);

    // ----- layer 1 (input-space aggregation) -----
    prep1_kernel<<<1, 64>>>(W1, as1, ad1, proj);
    alpha1_kernel<<<gridAlpha1, B>>>(x, proj, asrc, adst, N);
    gather1_kernel<<<gridGather, B>>>(offs, csr_src, asrc, adst, x, agg, dsum, N);
    post1_kernel<<<gridPost1, B>>>(agg, dsum, W1, b1, bufB, N);

    // ----- layer 2 -----
    transform_kernel<256><<<gridT, B>>>(bufB, W2, bufA, N);
    alpha_kernel<<<gridAlpha, B>>>(bufA, as2, ad2, asrc, adst, N);
    gather_kernel<<<gridGather, B>>>(offs, csr_src, asrc, adst, bufA, bufB, N);

    // ----- head-mean + classifier -----
    final_kernel<<<gridFinal, B>>>(bufB, b2, Wc, bc, out, N);
}